// round 15
// baseline (speedup 1.0000x reference)
#include <cuda_runtime.h>
#include <math.h>
#include <stdint.h>

// ---------------------------------------------------------------------------
// VSSBlock (VMamba) — round 15: scatter-merge. pass2 writes each direction's
// y directly to its final spatial slot (dir0 store, dirs1-3 atomicAdd), so
// the merge kernel reads ONE array instead of four. Scan core = round 14.
// Shapes: TB=16; H=W=56 -> L=3136; C=96; DI=192; N=16; R=6; K=4.
// ---------------------------------------------------------------------------

#define TBc   16
#define HH    56
#define WW    56
#define LL    3136
#define Cc    96
#define DIc   192
#define NSc   16
#define Rc    6
#define Kc    4
#define C38   38
#define C40   40              // padded row: dts[0:6), B[8:24), C[24:40)
#define M1c   (TBc*LL)        // 50176
#define SEG   98
#define NSEG  32
#define NCH   (TBc*Kc*DIc)    // 12288 channels
#define NCH0  (TBc*DIc)       // 3072 channels of direction 0

// ------------------------- scratch (device globals) ------------------------
__device__ float  g_xi  [(size_t)TBc*LL*DIc];       // (tb,l,d)  pre-conv
__device__ float  g_z   [(size_t)TBc*LL*DIc];       // (tb,l,d)  gate input
__device__ float  g_xs2 [(size_t)2*TBc*LL*DIc];     // (k2,tb,l,d) dirs 0,1
__device__ float  g_xdbl[(size_t)Kc*TBc*LL*C40];    // (k,tb,pos,40) dts|B|C
__device__ float  g_y2  [(size_t)TBc*LL*DIc];       // (tb,l,d) merged y (4 dirs)
__device__ float  g_y   [(size_t)TBc*LL*DIc];       // (tb,l,d) after LN+gate
__device__ float  g_xf2 [(size_t)TBc*LL*Cc];        // (tb,l,c) after residual 1
__device__ float  g_h1  [(size_t)TBc*LL*4*Cc];      // (tb,l,4C) MLP hidden
__device__ float  g_hend[(size_t)NCH*NSEG*NSc];     // (c,seg,n) local end state
__device__ float  g_rseg[(size_t)NCH*NSEG];         // (c,seg) R_seg | dt_tot
__device__ float  g_h0  [(size_t)NCH*NSEG*NSc];     // (c,seg,n) segment start

// ------------------------------- helpers -----------------------------------
__device__ __forceinline__ float siluf(float x) {
    return x / (1.0f + __expf(-x));
}
__device__ __forceinline__ float gelu_exactf(float x) {
    return 0.5f * x * (1.0f + erff(x * 0.70710678118654752f));
}
__device__ __forceinline__ uint32_t f2tf32(float x) {
    uint32_t r;
    asm("cvt.rna.tf32.f32 %0, %1;" : "=r"(r) : "f"(x));
    return r;
}
__device__ __forceinline__ void mma_tf32(float* d, const uint32_t* a, const uint32_t* b) {
    asm volatile(
        "mma.sync.aligned.m16n8k8.row.col.f32.tf32.tf32.f32 "
        "{%0,%1,%2,%3}, {%4,%5,%6,%7}, {%8,%9}, {%0,%1,%2,%3};\n"
        : "+f"(d[0]), "+f"(d[1]), "+f"(d[2]), "+f"(d[3])
        : "r"(a[0]), "r"(a[1]), "r"(a[2]), "r"(a[3]), "r"(b[0]), "r"(b[1]));
}

// dt projection + softplus + r = exp(-dt), from a broadcast x_dbl row
__device__ __forceinline__ void dt_from_row(
    const float* __restrict__ rowp, const float* __restrict__ wr, float dbias,
    float& dt, float& r)
{
    const float4 xq = *(const float4*)(rowp);
    const float2 xr = *(const float2*)(rowp + 4);
    float xv = dbias;
    xv = fmaf(xq.x, wr[0], xv); xv = fmaf(xq.y, wr[1], xv);
    xv = fmaf(xq.z, wr[2], xv); xv = fmaf(xq.w, wr[3], xv);
    xv = fmaf(xr.x, wr[4], xv); xv = fmaf(xr.y, wr[5], xv);
    if (xv > 20.0f) {
        dt = xv;
        r  = __expf(-xv);
    } else {
        float ex = __expf(xv);
        r  = __fdividef(1.0f, 1.0f + ex);    // exp(-softplus(x))
        dt = __logf(1.0f + ex);
    }
}

// decay powers e[n] = r^(n+1), tree form
__device__ __forceinline__ void epow16(float r, float* e)
{
    const float r2 = r * r, r4 = r2 * r2, r8 = r4 * r4;
    e[0]  = r;        e[1]  = r2;       e[2]  = r2 * r;   e[3]  = r4;
    e[4]  = r4 * r;   e[5]  = r4 * r2;  e[6]  = e[5] * r; e[7]  = r8;
    e[8]  = r8 * r;   e[9]  = r8 * r2;  e[10] = e[9] * r; e[11] = r8 * r4;
    e[12] = e[11] * r; e[13] = e[11] * r2; e[14] = e[13] * r; e[15] = r8 * r8;
}

// ------------------------------ TF32 GEMM -----------------------------------
enum { EPI_INPROJ = 0, EPI_XPROJ = 1, EPI_OUTPROJ = 2, EPI_FC1 = 3, EPI_FC2 = 4 };

template <int EPI>
__global__ __launch_bounds__(256) void mma_gemm_kernel(
    const float* __restrict__ A, const float* __restrict__ W,
    const float* __restrict__ bias, const float* __restrict__ resid,
    float* __restrict__ out, int M, int N, int Kdim)
{
    constexpr int BM = 128, BN = 64, BK = 16;
    __shared__ uint2 Qa[2][BM][4];   // 8 KB
    __shared__ uint2 Qb[2][BN][4];   // 4 KB

    const int tid = threadIdx.x;
    const int m0 = blockIdx.y * BM;
    const int n0 = blockIdx.x * BN;

    size_t zbase = 0;
    const float* Wb = W;
    const float* Ab = A;
    if (EPI == EPI_XPROJ) {
        const int kz = blockIdx.z;
        zbase = (size_t)kz * (size_t)M;
        Wb = W + (size_t)kz * C38 * DIc;
        Ab = A + (size_t)((kz < 2) ? kz : (kz - 2)) * (size_t)M * Kdim;
    }

    const int lmA = tid >> 1;                 // 0..127
    const int kA  = (tid & 1) * 8;            // 0 or 8
    const int lnW = tid >> 2;                 // 0..63
    const int kW  = (tid & 3) * 4;            // 0,4,8,12

    int srow = m0 + lmA;
    if (EPI == EPI_XPROJ && blockIdx.z >= 2) {
        int tb = srow / LL;
        int l  = srow - tb * LL;
        srow = tb * LL + (LL - 1 - l);
    }
    const float* aptr = Ab + (size_t)srow * Kdim + kA;
    const float* wptr = Wb + (size_t)(n0 + lnW) * Kdim + kW;
    const bool wvalid = (n0 + lnW) < N;

    float4 av0 = *(const float4*)(aptr);
    float4 av1 = *(const float4*)(aptr + 4);
    float4 wv  = wvalid ? *(const float4*)(wptr) : make_float4(0.f, 0.f, 0.f, 0.f);

    const int wid = tid >> 5;
    const int wm  = wid & 3;
    const int wn  = wid >> 2;
    const int lane = tid & 31;
    const int gid = lane >> 2;
    const int tig = lane & 3;

    const int wkc8 = kA >> 3;
    const int wbc8 = kW >> 3;
    const int wbh  = (kW & 4) ? 1 : 0;

    float acc[2][4][4];
#pragma unroll
    for (int i = 0; i < 2; i++)
#pragma unroll
        for (int j = 0; j < 4; j++)
#pragma unroll
            for (int q = 0; q < 4; q++) acc[i][j][q] = 0.0f;

    for (int kt = 0; kt < Kdim; kt += BK) {
        Qa[wkc8][lmA][0] = make_uint2(f2tf32(av0.x), f2tf32(av1.x));
        Qa[wkc8][lmA][1] = make_uint2(f2tf32(av0.y), f2tf32(av1.y));
        Qa[wkc8][lmA][2] = make_uint2(f2tf32(av0.z), f2tf32(av1.z));
        Qa[wkc8][lmA][3] = make_uint2(f2tf32(av0.w), f2tf32(av1.w));
        {
            uint32_t* qb = (uint32_t*)&Qb[wbc8][lnW][0];
            qb[0 * 2 + wbh] = f2tf32(wv.x);
            qb[1 * 2 + wbh] = f2tf32(wv.y);
            qb[2 * 2 + wbh] = f2tf32(wv.z);
            qb[3 * 2 + wbh] = f2tf32(wv.w);
        }
        __syncthreads();

        if (kt + BK < Kdim) {
            av0 = *(const float4*)(aptr + kt + BK);
            av1 = *(const float4*)(aptr + kt + BK + 4);
            if (wvalid) wv = *(const float4*)(wptr + kt + BK);
        }

#pragma unroll
        for (int kc8 = 0; kc8 < 2; kc8++) {
            uint32_t afr[2][4];
#pragma unroll
            for (int mt = 0; mt < 2; mt++) {
                const int mb = wm * 32 + mt * 16 + gid;
                const uint2 p0 = Qa[kc8][mb][tig];
                const uint2 p1 = Qa[kc8][mb + 8][tig];
                afr[mt][0] = p0.x; afr[mt][1] = p1.x;
                afr[mt][2] = p0.y; afr[mt][3] = p1.y;
            }
            uint32_t bfr[4][2];
#pragma unroll
            for (int nt = 0; nt < 4; nt++) {
                const uint2 pb = Qb[kc8][wn * 32 + nt * 8 + gid][tig];
                bfr[nt][0] = pb.x; bfr[nt][1] = pb.y;
            }
#pragma unroll
            for (int mt = 0; mt < 2; mt++)
#pragma unroll
                for (int nt = 0; nt < 4; nt++)
                    mma_tf32(acc[mt][nt], afr[mt], bfr[nt]);
        }
        __syncthreads();
    }

    auto store = [&](int gm, int gn, float v) {
        if (EPI == EPI_INPROJ) {
            if (gn < DIc)      g_xi[(size_t)gm * DIc + gn] = v;
            else               g_z [(size_t)gm * DIc + (gn - DIc)] = v;
        } else if (EPI == EPI_XPROJ) {
            if (gn < C38)      g_xdbl[(zbase + gm) * C40 + (gn < 6 ? gn : gn + 2)] = v;
        } else if (EPI == EPI_OUTPROJ) {
            if (gn < Cc)       g_xf2[(size_t)gm * Cc + gn] =
                                   resid[(size_t)gm * Cc + gn] + v;
        } else if (EPI == EPI_FC1) {
            g_h1[(size_t)gm * (4 * Cc) + gn] = gelu_exactf(v + bias[gn]);
        } else if (EPI == EPI_FC2) {
            if (gn < Cc)       out[(size_t)gm * Cc + gn] =
                                   g_xf2[(size_t)gm * Cc + gn] + v + bias[gn];
        }
    };

#pragma unroll
    for (int mt = 0; mt < 2; mt++) {
        const int r0 = m0 + wm * 32 + mt * 16 + gid;
#pragma unroll
        for (int nt = 0; nt < 4; nt++) {
            const int c0 = n0 + wn * 32 + nt * 8 + 2 * tig;
            store(r0,     c0,     acc[mt][nt][0]);
            store(r0,     c0 + 1, acc[mt][nt][1]);
            store(r0 + 8, c0,     acc[mt][nt][2]);
            store(r0 + 8, c0 + 1, acc[mt][nt][3]);
        }
    }
}

// --------------------- depthwise conv 3x3 + SiLU + cross-scan ---------------
__global__ __launch_bounds__(192) void conv_scan_kernel(
    const float* __restrict__ cw, const float* __restrict__ cb)
{
    const int tb = blockIdx.x / HH;
    const int h  = blockIdx.x % HH;
    const int d  = threadIdx.x;

    float wg[9];
#pragma unroll
    for (int i = 0; i < 9; i++) wg[i] = cw[d * 9 + i];
    const float bias = cb[d];

    const float* xin = g_xi + (size_t)tb * LL * DIc + d;

    float c0[3], c1[3], c2[3];
    auto loadcol = [&](int wc, float* col) {
#pragma unroll
        for (int r = 0; r < 3; r++) {
            int hh = h - 1 + r;
            col[r] = (hh >= 0 && hh < HH && wc >= 0 && wc < WW)
                     ? xin[(size_t)(hh * WW + wc) * DIc] : 0.0f;
        }
    };
    loadcol(-1, c0);
    loadcol(0, c1);

    for (int w = 0; w < WW; w++) {
        loadcol(w + 1, c2);
        float acc = bias;
        acc += c0[0] * wg[0] + c1[0] * wg[1] + c2[0] * wg[2];
        acc += c0[1] * wg[3] + c1[1] * wg[4] + c2[1] * wg[5];
        acc += c0[2] * wg[6] + c1[2] * wg[7] + c2[2] * wg[8];
        float v = siluf(acc);

        int lrm = h * WW + w;
        int lcm = w * HH + h;
        g_xs2[((size_t)(0 * TBc + tb) * LL + lrm) * DIc + d] = v;
        g_xs2[((size_t)(1 * TBc + tb) * LL + lcm) * DIc + d] = v;

        c0[0] = c1[0]; c0[1] = c1[1]; c0[2] = c1[2];
        c1[0] = c2[0]; c1[1] = c2[1]; c1[2] = c2[2];
    }
}

// ------------------------- chunked selective scan ---------------------------
// One thread per (channel, segment). 16 states in registers, no shfl.

__device__ __forceinline__ bool pow_check(const float* A_logs, int ad)
{
    bool pw = true;
#pragma unroll
    for (int n = 0; n < NSc; n++)
        pw = pw && (fabsf(__expf(A_logs[ad * NSc + n]) - (float)(n + 1)) < 1e-5f);
    return pw;
}

// pass 1: state-only. Segments 0..NSEG-2 (last segment's h_end unused).
__global__ __launch_bounds__(128) void scan_pass1(
    const float* __restrict__ A_logs,
    const float* __restrict__ dtw, const float* __restrict__ dtb)
{
    const int t   = blockIdx.x * 128 + threadIdx.x;
    const int seg = t / NCH;               // 0..NSEG-2
    const int c   = t - seg * NCH;
    const int kb  = c / DIc;
    const int d   = c - kb * DIc;
    const int kz  = kb >> 4;
    const int tb  = kb & 15;
    const int ad  = kz * DIc + d;
    const bool pow_ok = pow_check(A_logs, ad);

    float wr[Rc];
    const float* wp = dtw + (size_t)ad * Rc;
#pragma unroll
    for (int r = 0; r < Rc; r++) wr[r] = wp[r];
    const float dbias = dtb[ad];

    const int p0 = seg * SEG;
    const float* up;
    int ustride;
    if (kz < 2) {
        up = g_xs2 + ((size_t)(kz * TBc + tb) * LL + p0) * DIc + d;
        ustride = DIc;
    } else {
        up = g_xs2 + ((size_t)((kz - 2) * TBc + tb) * LL + (LL - 1 - p0)) * DIc + d;
        ustride = -DIc;
    }
    const float* rowp = g_xdbl + ((size_t)kb * LL + p0) * C40;

    float h[NSc];
#pragma unroll
    for (int n = 0; n < NSc; n++) h[n] = 0.f;

    if (pow_ok) {
        float Rseg = 1.f;
        for (int i = 0; i < SEG; i++) {
            float dt, r;
            dt_from_row(rowp, wr, dbias, dt, r);
            const float du = dt * up[0];
            float e[NSc];
            epow16(r, e);
#pragma unroll
            for (int g = 0; g < 4; g++) {
                const float4 B = *(const float4*)(rowp + 8 + 4 * g);
                h[4*g+0] = fmaf(h[4*g+0], e[4*g+0], du * B.x);
                h[4*g+1] = fmaf(h[4*g+1], e[4*g+1], du * B.y);
                h[4*g+2] = fmaf(h[4*g+2], e[4*g+2], du * B.z);
                h[4*g+3] = fmaf(h[4*g+3], e[4*g+3], du * B.w);
            }
            Rseg *= r;
            up += ustride; rowp += C40;
        }
        g_rseg[(size_t)c * NSEG + seg] = Rseg;
    } else {
        float dtsum = 0.f;
        const float* Ap = A_logs + ad * NSc;
        for (int i = 0; i < SEG; i++) {
            float dt, r;
            dt_from_row(rowp, wr, dbias, dt, r);
            const float du = dt * up[0];
#pragma unroll
            for (int g = 0; g < 4; g++) {
                const float4 B  = *(const float4*)(rowp + 8 + 4 * g);
                const float4 Al = *(const float4*)(Ap + 4 * g);
                h[4*g+0] = fmaf(h[4*g+0], __expf(-dt * __expf(Al.x)), du * B.x);
                h[4*g+1] = fmaf(h[4*g+1], __expf(-dt * __expf(Al.y)), du * B.y);
                h[4*g+2] = fmaf(h[4*g+2], __expf(-dt * __expf(Al.z)), du * B.z);
                h[4*g+3] = fmaf(h[4*g+3], __expf(-dt * __expf(Al.w)), du * B.w);
            }
            dtsum += dt;
            up += ustride; rowp += C40;
        }
        g_rseg[(size_t)c * NSEG + seg] = dtsum;
    }

    float* he = g_hend + ((size_t)c * NSEG + seg) * NSc;
#pragma unroll
    for (int g = 0; g < 4; g++)
        *(float4*)(he + 4 * g) = make_float4(h[4*g], h[4*g+1], h[4*g+2], h[4*g+3]);
}

// prefix over segments: h0[s] = E_end[s-1] ⊙ h0[s-1] + h_end[s-1]
__global__ __launch_bounds__(128) void scan_prefix(const float* __restrict__ A_logs)
{
    const int c  = blockIdx.x * 128 + threadIdx.x;   // 12288 threads
    const int kb = c / DIc;
    const int d  = c - kb * DIc;
    const int kz = kb >> 4;
    const int ad = kz * DIc + d;
    const bool pow_ok = pow_check(A_logs, ad);

    float h[NSc];
#pragma unroll
    for (int n = 0; n < NSc; n++) h[n] = 0.f;

    float* h0p = g_h0 + (size_t)c * NSEG * NSc;
#pragma unroll
    for (int g = 0; g < 4; g++)
        *(float4*)(h0p + 4 * g) = make_float4(0.f, 0.f, 0.f, 0.f);

    const float* hep = g_hend + (size_t)c * NSEG * NSc;
    for (int sg = 0; sg < NSEG - 1; sg++) {
        const float v = g_rseg[(size_t)c * NSEG + sg];
        if (pow_ok) {
            float e[NSc];
            epow16(v, e);                                 // v = R_seg
#pragma unroll
            for (int n = 0; n < NSc; n++)
                h[n] = fmaf(h[n], e[n], hep[sg * NSc + n]);
        } else {
            const float* Ap = A_logs + ad * NSc;
#pragma unroll
            for (int n = 0; n < NSc; n++) {
                float e = __expf(-v * __expf(Ap[n]));     // v = dt_tot
                h[n] = fmaf(h[n], e, hep[sg * NSc + n]);
            }
        }
        float* hn = h0p + (sg + 1) * NSc;
#pragma unroll
        for (int g = 0; g < 4; g++)
            *(float4*)(hn + 4 * g) = make_float4(h[4*g], h[4*g+1], h[4*g+2], h[4*g+3]);
    }
}

// pass 2: full recurrence seeded by h0; writes y to FINAL spatial slot.
// MODE 0: direction 0 (plain store, bijective -> initializes g_y2).
// MODE 1: directions 1..3 (atomicAdd into g_y2).
template <int MODE>
__global__ __launch_bounds__(128) void scan_pass2(
    const float* __restrict__ A_logs, const float* __restrict__ Ds,
    const float* __restrict__ dtw, const float* __restrict__ dtb)
{
    const int NCHsub = (MODE == 0) ? NCH0 : (NCH - NCH0);
    const int t   = blockIdx.x * 128 + threadIdx.x;
    const int seg = t / NCHsub;
    const int cl  = t - seg * NCHsub;
    const int c   = (MODE == 0) ? cl : (NCH0 + cl);
    const int kb  = c / DIc;
    const int d   = c - kb * DIc;
    const int kz  = kb >> 4;
    const int tb  = kb & 15;
    const int ad  = kz * DIc + d;
    const bool pow_ok = pow_check(A_logs, ad);
    const float Dv = Ds[ad];

    float wr[Rc];
    const float* wp = dtw + (size_t)ad * Rc;
#pragma unroll
    for (int r = 0; r < Rc; r++) wr[r] = wp[r];
    const float dbias = dtb[ad];

    float h[NSc];
    const float* h0p = g_h0 + ((size_t)c * NSEG + seg) * NSc;
#pragma unroll
    for (int g = 0; g < 4; g++) {
        float4 v = *(const float4*)(h0p + 4 * g);
        h[4*g] = v.x; h[4*g+1] = v.y; h[4*g+2] = v.z; h[4*g+3] = v.w;
    }

    const int p0 = seg * SEG;
    const float* up;
    int ustride;
    if (kz < 2) {
        up = g_xs2 + ((size_t)(kz * TBc + tb) * LL + p0) * DIc + d;
        ustride = DIc;
    } else {
        up = g_xs2 + ((size_t)((kz - 2) * TBc + tb) * LL + (LL - 1 - p0)) * DIc + d;
        ustride = -DIc;
    }
    const float* rowp = g_xdbl + ((size_t)kb * LL + p0) * C40;

    // spatial index state (warp-uniform kz; incremental remap)
    int l = 0, hh = 0, wv2 = 0;
    if (kz == 0) {
        l = p0;
    } else if (kz == 1) {
        wv2 = p0 / HH; hh = p0 - wv2 * HH; l = hh * WW + wv2;
    } else if (kz == 2) {
        l = LL - 1 - p0;
    } else {
        int j = LL - 1 - p0;
        wv2 = j / HH; hh = j - wv2 * HH; l = hh * WW + wv2;
    }
    float* ybase = g_y2 + (size_t)tb * LL * DIc + d;

    const float* Ap = A_logs + ad * NSc;
    for (int i = 0; i < SEG; i++) {
        float dt, r;
        dt_from_row(rowp, wr, dbias, dt, r);
        const float u  = up[0];
        const float du = dt * u;
        float acc = 0.f;
        if (pow_ok) {
            float e[NSc];
            epow16(r, e);
#pragma unroll
            for (int g = 0; g < 4; g++) {
                const float4 B = *(const float4*)(rowp + 8 + 4 * g);
                const float4 C = *(const float4*)(rowp + 24 + 4 * g);
                h[4*g+0] = fmaf(h[4*g+0], e[4*g+0], du * B.x); acc = fmaf(h[4*g+0], C.x, acc);
                h[4*g+1] = fmaf(h[4*g+1], e[4*g+1], du * B.y); acc = fmaf(h[4*g+1], C.y, acc);
                h[4*g+2] = fmaf(h[4*g+2], e[4*g+2], du * B.z); acc = fmaf(h[4*g+2], C.z, acc);
                h[4*g+3] = fmaf(h[4*g+3], e[4*g+3], du * B.w); acc = fmaf(h[4*g+3], C.w, acc);
            }
        } else {
#pragma unroll
            for (int g = 0; g < 4; g++) {
                const float4 B  = *(const float4*)(rowp + 8 + 4 * g);
                const float4 C  = *(const float4*)(rowp + 24 + 4 * g);
                const float4 Al = *(const float4*)(Ap + 4 * g);
                h[4*g+0] = fmaf(h[4*g+0], __expf(-dt * __expf(Al.x)), du * B.x); acc = fmaf(h[4*g+0], C.x, acc);
                h[4*g+1] = fmaf(h[4*g+1], __expf(-dt * __expf(Al.y)), du * B.y); acc = fmaf(h[4*g+1], C.y, acc);
                h[4*g+2] = fmaf(h[4*g+2], __expf(-dt * __expf(Al.z)), du * B.z); acc = fmaf(h[4*g+2], C.z, acc);
                h[4*g+3] = fmaf(h[4*g+3], __expf(-dt * __expf(Al.w)), du * B.w); acc = fmaf(h[4*g+3], C.w, acc);
            }
        }

        const float yv = acc + Dv * u;
        if (MODE == 0) {
            ybase[(size_t)l * DIc] = yv;
        } else {
            atomicAdd(&ybase[(size_t)l * DIc], yv);
        }

        // advance spatial index
        if (kz == 0) {
            ++l;
        } else if (kz == 1) {
            if (++hh == HH) { hh = 0; ++wv2; }
            l = hh * WW + wv2;
        } else if (kz == 2) {
            --l;
        } else {
            if (--hh < 0) { hh = HH - 1; --wv2; }
            l = hh * WW + wv2;
        }
        up += ustride; rowp += C40;
    }
}

// ----------------- LayerNorm + SiLU gate (merged y already in g_y2) ---------
__global__ __launch_bounds__(192) void merge_ln_gate_kernel(
    const float* __restrict__ ln_g, const float* __restrict__ ln_b)
{
    const int bid = blockIdx.x;
    const int d   = threadIdx.x;
    const size_t base = (size_t)bid * DIc;

    float y = g_y2[base + d];

    float s = y, s2 = y * y;
#pragma unroll
    for (int o = 16; o > 0; o >>= 1) {
        s  += __shfl_xor_sync(0xffffffffu, s,  o);
        s2 += __shfl_xor_sync(0xffffffffu, s2, o);
    }
    __shared__ float sh[14];
    const int wid = d >> 5;
    if ((d & 31) == 0) { sh[wid] = s; sh[6 + wid] = s2; }
    __syncthreads();
    if (d == 0) {
        float ts = 0.f, ts2 = 0.f;
#pragma unroll
        for (int i = 0; i < 6; i++) { ts += sh[i]; ts2 += sh[6 + i]; }
        float mu  = ts * (1.0f / 192.0f);
        float var = ts2 * (1.0f / 192.0f) - mu * mu;
        sh[12] = mu;
        sh[13] = rsqrtf(var + 1e-5f);
    }
    __syncthreads();
    float mu = sh[12], rs = sh[13];

    float yn = (y - mu) * rs * ln_g[d] + ln_b[d];
    float zv = g_z[base + d];
    g_y[base + d] = yn * siluf(zv);
}

// ------------------------------- launch -------------------------------------
extern "C" void kernel_launch(void* const* d_in, const int* in_sizes, int n_in,
                              void* d_out, int out_size)
{
    const float* x          = (const float*)d_in[0];
    const float* in_proj_w  = (const float*)d_in[1];
    const float* conv_w     = (const float*)d_in[2];
    const float* conv_b     = (const float*)d_in[3];
    const float* x_proj_w   = (const float*)d_in[4];
    const float* dt_w       = (const float*)d_in[5];
    const float* dt_b       = (const float*)d_in[6];
    const float* A_logs     = (const float*)d_in[7];
    const float* Ds         = (const float*)d_in[8];
    const float* ln_g       = (const float*)d_in[9];
    const float* ln_b       = (const float*)d_in[10];
    const float* out_proj_w = (const float*)d_in[11];
    const float* fc1_w      = (const float*)d_in[12];
    const float* fc1_b      = (const float*)d_in[13];
    const float* fc2_w      = (const float*)d_in[14];
    const float* fc2_b      = (const float*)d_in[15];
    float* out = (float*)d_out;

    float *pxs2 = nullptr, *py = nullptr, *pxf2 = nullptr, *ph1 = nullptr;
    cudaGetSymbolAddress((void**)&pxs2, g_xs2);
    cudaGetSymbolAddress((void**)&py,   g_y);
    cudaGetSymbolAddress((void**)&pxf2, g_xf2);
    cudaGetSymbolAddress((void**)&ph1,  g_h1);

    // 1. in_proj: (50176 x 96) @ (384 x 96)^T -> xi | z
    mma_gemm_kernel<EPI_INPROJ><<<dim3(6, M1c / 128), 256>>>(
        x, in_proj_w, nullptr, nullptr, nullptr, M1c, 384, Cc);

    // 2. depthwise conv + SiLU + cross-scan (dirs 0,1 only)
    conv_scan_kernel<<<TBc * HH, 192>>>(conv_w, conv_b);

    // 3. x_proj: per-direction (50176 x 192) @ (38 x 192)^T -> dts|B|C (padded)
    mma_gemm_kernel<EPI_XPROJ><<<dim3(1, M1c / 128, Kc), 256>>>(
        pxs2, x_proj_w, nullptr, nullptr, nullptr, M1c, C38, DIc);

    // 4. chunked selective scan: state pass, prefix, scatter-write passes
    scan_pass1<<<(NCH * (NSEG - 1)) / 128, 128>>>(A_logs, dt_w, dt_b);
    scan_prefix<<<NCH / 128, 128>>>(A_logs);
    scan_pass2<0><<<(NCH0 * NSEG) / 128, 128>>>(A_logs, Ds, dt_w, dt_b);
    scan_pass2<1><<<((NCH - NCH0) * NSEG) / 128, 128>>>(A_logs, Ds, dt_w, dt_b);

    // 5. LayerNorm + SiLU(z) gate (y already merged)
    merge_ln_gate_kernel<<<TBc * LL, 192>>>(ln_g, ln_b);

    // 6. out_proj + residual 1 -> g_xf2
    mma_gemm_kernel<EPI_OUTPROJ><<<dim3(2, M1c / 128), 256>>>(
        py, out_proj_w, nullptr, x, nullptr, M1c, Cc, DIc);

    // 7. fc1 + bias + exact GELU -> g_h1
    mma_gemm_kernel<EPI_FC1><<<dim3(6, M1c / 128), 256>>>(
        pxf2, fc1_w, fc1_b, nullptr, nullptr, M1c, 4 * Cc, Cc);

    // 8. fc2 + bias + residual 2 -> d_out
    mma_gemm_kernel<EPI_FC2><<<dim3(2, M1c / 128), 256>>>(
        ph1, fc2_w, fc2_b, nullptr, out, M1c, Cc, 4 * Cc);
}

// round 16
// speedup vs baseline: 1.1737x; 1.1737x over previous
#include <cuda_runtime.h>
#include <cuda_bf16.h>
#include <math.h>
#include <stdint.h>

// ---------------------------------------------------------------------------
// VSSBlock (VMamba) — round 16: R14 baseline with BF16 tensor-core GEMMs
// (mma.sync.m16n8k16, fp32 accumulate). Scan/conv/merge identical to R14.
// Shapes: TB=16; H=W=56 -> L=3136; C=96; DI=192; N=16; R=6; K=4.
// ---------------------------------------------------------------------------

#define TBc   16
#define HH    56
#define WW    56
#define LL    3136
#define Cc    96
#define DIc   192
#define NSc   16
#define Rc    6
#define Kc    4
#define C38   38
#define C40   40              // padded row: dts[0:6), B[8:24), C[24:40)
#define M1c   (TBc*LL)        // 50176
#define SEG   98
#define NSEG  32
#define NCH   (TBc*Kc*DIc)    // 12288 channels

// ------------------------- scratch (device globals) ------------------------
__device__ float  g_xi  [(size_t)TBc*LL*DIc];       // (tb,l,d)  pre-conv
__device__ float  g_z   [(size_t)TBc*LL*DIc];       // (tb,l,d)  gate input
__device__ float  g_xs2 [(size_t)2*TBc*LL*DIc];     // (k2,tb,l,d) dirs 0,1
__device__ float  g_xdbl[(size_t)Kc*TBc*LL*C40];    // (k,tb,pos,40) dts|B|C
__device__ float  g_ysT [(size_t)Kc*TBc*LL*DIc];    // (k,tb,pos,d) scan out
__device__ float  g_y   [(size_t)TBc*LL*DIc];       // (tb,l,d) merged+LN+gated
__device__ float  g_xf2 [(size_t)TBc*LL*Cc];        // (tb,l,c) after residual 1
__device__ float  g_h1  [(size_t)TBc*LL*4*Cc];      // (tb,l,4C) MLP hidden
__device__ float  g_hend[(size_t)NCH*NSEG*NSc];     // (c,seg,n) local end state
__device__ float  g_rseg[(size_t)NCH*NSEG];         // (c,seg) R_seg | dt_tot
__device__ float  g_h0  [(size_t)NCH*NSEG*NSc];     // (c,seg,n) segment start

// ------------------------------- helpers -----------------------------------
__device__ __forceinline__ float siluf(float x) {
    return x / (1.0f + __expf(-x));
}
__device__ __forceinline__ float gelu_exactf(float x) {
    return 0.5f * x * (1.0f + erff(x * 0.70710678118654752f));
}
// pack two floats -> bf16x2 (lo in [15:0], hi in [31:16])
__device__ __forceinline__ uint32_t f2bf2(float lo, float hi) {
    uint32_t r;
    asm("cvt.rn.bf16x2.f32 %0, %1, %2;" : "=r"(r) : "f"(hi), "f"(lo));
    return r;
}
__device__ __forceinline__ void mma_bf16(float* d, const uint32_t* a, const uint32_t* b) {
    asm volatile(
        "mma.sync.aligned.m16n8k16.row.col.f32.bf16.bf16.f32 "
        "{%0,%1,%2,%3}, {%4,%5,%6,%7}, {%8,%9}, {%0,%1,%2,%3};\n"
        : "+f"(d[0]), "+f"(d[1]), "+f"(d[2]), "+f"(d[3])
        : "r"(a[0]), "r"(a[1]), "r"(a[2]), "r"(a[3]), "r"(b[0]), "r"(b[1]));
}

// dt projection + softplus + r = exp(-dt), from a broadcast x_dbl row
__device__ __forceinline__ void dt_from_row(
    const float* __restrict__ rowp, const float* __restrict__ wr, float dbias,
    float& dt, float& r)
{
    const float4 xq = *(const float4*)(rowp);
    const float2 xr = *(const float2*)(rowp + 4);
    float xv = dbias;
    xv = fmaf(xq.x, wr[0], xv); xv = fmaf(xq.y, wr[1], xv);
    xv = fmaf(xq.z, wr[2], xv); xv = fmaf(xq.w, wr[3], xv);
    xv = fmaf(xr.x, wr[4], xv); xv = fmaf(xr.y, wr[5], xv);
    if (xv > 20.0f) {
        dt = xv;
        r  = __expf(-xv);
    } else {
        float ex = __expf(xv);
        r  = __fdividef(1.0f, 1.0f + ex);    // exp(-softplus(x))
        dt = __logf(1.0f + ex);
    }
}

// decay powers e[n] = r^(n+1), tree form
__device__ __forceinline__ void epow16(float r, float* e)
{
    const float r2 = r * r, r4 = r2 * r2, r8 = r4 * r4;
    e[0]  = r;        e[1]  = r2;       e[2]  = r2 * r;   e[3]  = r4;
    e[4]  = r4 * r;   e[5]  = r4 * r2;  e[6]  = e[5] * r; e[7]  = r8;
    e[8]  = r8 * r;   e[9]  = r8 * r2;  e[10] = e[9] * r; e[11] = r8 * r4;
    e[12] = e[11] * r; e[13] = e[11] * r2; e[14] = e[13] * r; e[15] = r8 * r8;
}

// ------------------------------ BF16 GEMM -----------------------------------
// out[m,n] = sum_k A[m,k] * W[n,k];  A: MxK row-major, W: NxK row-major.
// BM=128, BN=64, BK=16, 256 threads = 8 warps (4m x 2n), warp tile 32x32
// via 2x4 m16n8k16 mma. Smem: bf16x2 pairs, Q[row][tig] = {pair tig, tig+4}.
enum { EPI_INPROJ = 0, EPI_XPROJ = 1, EPI_OUTPROJ = 2, EPI_FC1 = 3, EPI_FC2 = 4 };

template <int EPI>
__global__ __launch_bounds__(256) void mma_gemm_kernel(
    const float* __restrict__ A, const float* __restrict__ W,
    const float* __restrict__ bias, const float* __restrict__ resid,
    float* __restrict__ out, int M, int N, int Kdim)
{
    constexpr int BM = 128, BN = 64, BK = 16;
    __shared__ uint2 Qa[BM][4];   // 4 KB
    __shared__ uint2 Qb[BN][4];   // 2 KB

    const int tid = threadIdx.x;
    const int m0 = blockIdx.y * BM;
    const int n0 = blockIdx.x * BN;

    size_t zbase = 0;
    const float* Wb = W;
    const float* Ab = A;
    if (EPI == EPI_XPROJ) {
        const int kz = blockIdx.z;
        zbase = (size_t)kz * (size_t)M;
        Wb = W + (size_t)kz * C38 * DIc;
        Ab = A + (size_t)((kz < 2) ? kz : (kz - 2)) * (size_t)M * Kdim;
    }

    const int lmA = tid >> 1;                 // 0..127
    const int kA  = (tid & 1) * 8;            // 0 or 8
    const int lnW = tid >> 2;                 // 0..63
    const int kW  = (tid & 3) * 4;            // 0,4,8,12

    int srow = m0 + lmA;
    if (EPI == EPI_XPROJ && blockIdx.z >= 2) {
        int tb = srow / LL;
        int l  = srow - tb * LL;
        srow = tb * LL + (LL - 1 - l);
    }
    const float* aptr = Ab + (size_t)srow * Kdim + kA;
    const float* wptr = Wb + (size_t)(n0 + lnW) * Kdim + kW;
    const bool wvalid = (n0 + lnW) < N;

    float4 av0 = *(const float4*)(aptr);
    float4 av1 = *(const float4*)(aptr + 4);
    float4 wv  = wvalid ? *(const float4*)(wptr) : make_float4(0.f, 0.f, 0.f, 0.f);

    const int wid = tid >> 5;
    const int wm  = wid & 3;
    const int wn  = wid >> 2;
    const int lane = tid & 31;
    const int gid = lane >> 2;
    const int tig = lane & 3;

    const int ahalf = kA >> 3;                // A loader component half
    const int bhalf = kW >> 3;                // B loader component half
    const int bs0   = (kW & 7) >> 1;          // 0 or 2

    float acc[2][4][4];
#pragma unroll
    for (int i = 0; i < 2; i++)
#pragma unroll
        for (int j = 0; j < 4; j++)
#pragma unroll
            for (int q = 0; q < 4; q++) acc[i][j][q] = 0.0f;

    for (int kt = 0; kt < Kdim; kt += BK) {
        {
            uint32_t* qa = (uint32_t*)&Qa[lmA][0];
            qa[0 * 2 + ahalf] = f2bf2(av0.x, av0.y);
            qa[1 * 2 + ahalf] = f2bf2(av0.z, av0.w);
            qa[2 * 2 + ahalf] = f2bf2(av1.x, av1.y);
            qa[3 * 2 + ahalf] = f2bf2(av1.z, av1.w);
        }
        {
            uint32_t* qb = (uint32_t*)&Qb[lnW][0];
            qb[(bs0 + 0) * 2 + bhalf] = f2bf2(wv.x, wv.y);
            qb[(bs0 + 1) * 2 + bhalf] = f2bf2(wv.z, wv.w);
        }
        __syncthreads();

        if (kt + BK < Kdim) {
            av0 = *(const float4*)(aptr + kt + BK);
            av1 = *(const float4*)(aptr + kt + BK + 4);
            if (wvalid) wv = *(const float4*)(wptr + kt + BK);
        }

        uint32_t afr[2][4];
#pragma unroll
        for (int mt = 0; mt < 2; mt++) {
            const int mb = wm * 32 + mt * 16 + gid;
            const uint2 p0 = Qa[mb][tig];
            const uint2 p1 = Qa[mb + 8][tig];
            afr[mt][0] = p0.x; afr[mt][1] = p1.x;
            afr[mt][2] = p0.y; afr[mt][3] = p1.y;
        }
        uint32_t bfr[4][2];
#pragma unroll
        for (int nt = 0; nt < 4; nt++) {
            const uint2 pb = Qb[wn * 32 + nt * 8 + gid][tig];
            bfr[nt][0] = pb.x; bfr[nt][1] = pb.y;
        }
#pragma unroll
        for (int mt = 0; mt < 2; mt++)
#pragma unroll
            for (int nt = 0; nt < 4; nt++)
                mma_bf16(acc[mt][nt], afr[mt], bfr[nt]);
        __syncthreads();
    }

    auto store = [&](int gm, int gn, float v) {
        if (EPI == EPI_INPROJ) {
            if (gn < DIc)      g_xi[(size_t)gm * DIc + gn] = v;
            else               g_z [(size_t)gm * DIc + (gn - DIc)] = v;
        } else if (EPI == EPI_XPROJ) {
            if (gn < C38)      g_xdbl[(zbase + gm) * C40 + (gn < 6 ? gn : gn + 2)] = v;
        } else if (EPI == EPI_OUTPROJ) {
            if (gn < Cc)       g_xf2[(size_t)gm * Cc + gn] =
                                   resid[(size_t)gm * Cc + gn] + v;
        } else if (EPI == EPI_FC1) {
            g_h1[(size_t)gm * (4 * Cc) + gn] = gelu_exactf(v + bias[gn]);
        } else if (EPI == EPI_FC2) {
            if (gn < Cc)       out[(size_t)gm * Cc + gn] =
                                   g_xf2[(size_t)gm * Cc + gn] + v + bias[gn];
        }
    };

#pragma unroll
    for (int mt = 0; mt < 2; mt++) {
        const int r0 = m0 + wm * 32 + mt * 16 + gid;
#pragma unroll
        for (int nt = 0; nt < 4; nt++) {
            const int c0 = n0 + wn * 32 + nt * 8 + 2 * tig;
            store(r0,     c0,     acc[mt][nt][0]);
            store(r0,     c0 + 1, acc[mt][nt][1]);
            store(r0 + 8, c0,     acc[mt][nt][2]);
            store(r0 + 8, c0 + 1, acc[mt][nt][3]);
        }
    }
}

// --------------------- depthwise conv 3x3 + SiLU + cross-scan ---------------
__global__ __launch_bounds__(192) void conv_scan_kernel(
    const float* __restrict__ cw, const float* __restrict__ cb)
{
    const int tb = blockIdx.x / HH;
    const int h  = blockIdx.x % HH;
    const int d  = threadIdx.x;

    float wg[9];
#pragma unroll
    for (int i = 0; i < 9; i++) wg[i] = cw[d * 9 + i];
    const float bias = cb[d];

    const float* xin = g_xi + (size_t)tb * LL * DIc + d;

    float c0[3], c1[3], c2[3];
    auto loadcol = [&](int wc, float* col) {
#pragma unroll
        for (int r = 0; r < 3; r++) {
            int hh = h - 1 + r;
            col[r] = (hh >= 0 && hh < HH && wc >= 0 && wc < WW)
                     ? xin[(size_t)(hh * WW + wc) * DIc] : 0.0f;
        }
    };
    loadcol(-1, c0);
    loadcol(0, c1);

    for (int w = 0; w < WW; w++) {
        loadcol(w + 1, c2);
        float acc = bias;
        acc += c0[0] * wg[0] + c1[0] * wg[1] + c2[0] * wg[2];
        acc += c0[1] * wg[3] + c1[1] * wg[4] + c2[1] * wg[5];
        acc += c0[2] * wg[6] + c1[2] * wg[7] + c2[2] * wg[8];
        float v = siluf(acc);

        int lrm = h * WW + w;
        int lcm = w * HH + h;
        g_xs2[((size_t)(0 * TBc + tb) * LL + lrm) * DIc + d] = v;
        g_xs2[((size_t)(1 * TBc + tb) * LL + lcm) * DIc + d] = v;

        c0[0] = c1[0]; c0[1] = c1[1]; c0[2] = c1[2];
        c1[0] = c2[0]; c1[1] = c2[1]; c1[2] = c2[2];
    }
}

// ------------------------- chunked selective scan ---------------------------
// One thread per (channel, segment). 16 states in registers, no shfl.
// dt computed inline from the broadcast x_dbl row (no sideband).

__device__ __forceinline__ bool pow_check(const float* A_logs, int ad)
{
    bool pw = true;
#pragma unroll
    for (int n = 0; n < NSc; n++)
        pw = pw && (fabsf(__expf(A_logs[ad * NSc + n]) - (float)(n + 1)) < 1e-5f);
    return pw;
}

// pass 1: state-only. Segments 0..NSEG-2 (last segment's h_end unused).
__global__ __launch_bounds__(128) void scan_pass1(
    const float* __restrict__ A_logs,
    const float* __restrict__ dtw, const float* __restrict__ dtb)
{
    const int t   = blockIdx.x * 128 + threadIdx.x;
    const int seg = t / NCH;               // 0..NSEG-2
    const int c   = t - seg * NCH;
    const int kb  = c / DIc;
    const int d   = c - kb * DIc;
    const int kz  = kb >> 4;
    const int tb  = kb & 15;
    const int ad  = kz * DIc + d;
    const bool pow_ok = pow_check(A_logs, ad);

    float wr[Rc];
    const float* wp = dtw + (size_t)ad * Rc;
#pragma unroll
    for (int r = 0; r < Rc; r++) wr[r] = wp[r];
    const float dbias = dtb[ad];

    const int p0 = seg * SEG;
    const float* up;
    int ustride;
    if (kz < 2) {
        up = g_xs2 + ((size_t)(kz * TBc + tb) * LL + p0) * DIc + d;
        ustride = DIc;
    } else {
        up = g_xs2 + ((size_t)((kz - 2) * TBc + tb) * LL + (LL - 1 - p0)) * DIc + d;
        ustride = -DIc;
    }
    const float* rowp = g_xdbl + ((size_t)kb * LL + p0) * C40;

    float h[NSc];
#pragma unroll
    for (int n = 0; n < NSc; n++) h[n] = 0.f;

    if (pow_ok) {
        float Rseg = 1.f;
        for (int i = 0; i < SEG; i++) {
            float dt, r;
            dt_from_row(rowp, wr, dbias, dt, r);
            const float du = dt * up[0];
            float e[NSc];
            epow16(r, e);
#pragma unroll
            for (int g = 0; g < 4; g++) {
                const float4 B = *(const float4*)(rowp + 8 + 4 * g);
                h[4*g+0] = fmaf(h[4*g+0], e[4*g+0], du * B.x);
                h[4*g+1] = fmaf(h[4*g+1], e[4*g+1], du * B.y);
                h[4*g+2] = fmaf(h[4*g+2], e[4*g+2], du * B.z);
                h[4*g+3] = fmaf(h[4*g+3], e[4*g+3], du * B.w);
            }
            Rseg *= r;
            up += ustride; rowp += C40;
        }
        g_rseg[(size_t)c * NSEG + seg] = Rseg;
    } else {
        float dtsum = 0.f;
        const float* Ap = A_logs + ad * NSc;
        for (int i = 0; i < SEG; i++) {
            float dt, r;
            dt_from_row(rowp, wr, dbias, dt, r);
            const float du = dt * up[0];
#pragma unroll
            for (int g = 0; g < 4; g++) {
                const float4 B  = *(const float4*)(rowp + 8 + 4 * g);
                const float4 Al = *(const float4*)(Ap + 4 * g);
                h[4*g+0] = fmaf(h[4*g+0], __expf(-dt * __expf(Al.x)), du * B.x);
                h[4*g+1] = fmaf(h[4*g+1], __expf(-dt * __expf(Al.y)), du * B.y);
                h[4*g+2] = fmaf(h[4*g+2], __expf(-dt * __expf(Al.z)), du * B.z);
                h[4*g+3] = fmaf(h[4*g+3], __expf(-dt * __expf(Al.w)), du * B.w);
            }
            dtsum += dt;
            up += ustride; rowp += C40;
        }
        g_rseg[(size_t)c * NSEG + seg] = dtsum;
    }

    float* he = g_hend + ((size_t)c * NSEG + seg) * NSc;
#pragma unroll
    for (int g = 0; g < 4; g++)
        *(float4*)(he + 4 * g) = make_float4(h[4*g], h[4*g+1], h[4*g+2], h[4*g+3]);
}

// prefix over segments: h0[s] = E_end[s-1] ⊙ h0[s-1] + h_end[s-1]
__global__ __launch_bounds__(128) void scan_prefix(const float* __restrict__ A_logs)
{
    const int c  = blockIdx.x * 128 + threadIdx.x;   // 12288 threads
    const int kb = c / DIc;
    const int d  = c - kb * DIc;
    const int kz = kb >> 4;
    const int ad = kz * DIc + d;
    const bool pow_ok = pow_check(A_logs, ad);

    float h[NSc];
#pragma unroll
    for (int n = 0; n < NSc; n++) h[n] = 0.f;

    float* h0p = g_h0 + (size_t)c * NSEG * NSc;
#pragma unroll
    for (int g = 0; g < 4; g++)
        *(float4*)(h0p + 4 * g) = make_float4(0.f, 0.f, 0.f, 0.f);

    const float* hep = g_hend + (size_t)c * NSEG * NSc;
    for (int sg = 0; sg < NSEG - 1; sg++) {
        const float v = g_rseg[(size_t)c * NSEG + sg];
        if (pow_ok) {
            float e[NSc];
            epow16(v, e);                                 // v = R_seg
#pragma unroll
            for (int n = 0; n < NSc; n++)
                h[n] = fmaf(h[n], e[n], hep[sg * NSc + n]);
        } else {
            const float* Ap = A_logs + ad * NSc;
#pragma unroll
            for (int n = 0; n < NSc; n++) {
                float e = __expf(-v * __expf(Ap[n]));     // v = dt_tot
                h[n] = fmaf(h[n], e, hep[sg * NSc + n]);
            }
        }
        float* hn = h0p + (sg + 1) * NSc;
#pragma unroll
        for (int g = 0; g < 4; g++)
            *(float4*)(hn + 4 * g) = make_float4(h[4*g], h[4*g+1], h[4*g+2], h[4*g+3]);
    }
}

// pass 2: full recurrence seeded by h0; writes y once (+ D skip).
__global__ __launch_bounds__(128) void scan_pass2(
    const float* __restrict__ A_logs, const float* __restrict__ Ds,
    const float* __restrict__ dtw, const float* __restrict__ dtb)
{
    const int t   = blockIdx.x * 128 + threadIdx.x;
    const int seg = t / NCH;
    const int c   = t - seg * NCH;
    const int kb  = c / DIc;
    const int d   = c - kb * DIc;
    const int kz  = kb >> 4;
    const int tb  = kb & 15;
    const int ad  = kz * DIc + d;
    const bool pow_ok = pow_check(A_logs, ad);
    const float Dv = Ds[ad];

    float wr[Rc];
    const float* wp = dtw + (size_t)ad * Rc;
#pragma unroll
    for (int r = 0; r < Rc; r++) wr[r] = wp[r];
    const float dbias = dtb[ad];

    float h[NSc];
    const float* h0p = g_h0 + ((size_t)c * NSEG + seg) * NSc;
#pragma unroll
    for (int g = 0; g < 4; g++) {
        float4 v = *(const float4*)(h0p + 4 * g);
        h[4*g] = v.x; h[4*g+1] = v.y; h[4*g+2] = v.z; h[4*g+3] = v.w;
    }

    const int p0 = seg * SEG;
    const float* up;
    int ustride;
    if (kz < 2) {
        up = g_xs2 + ((size_t)(kz * TBc + tb) * LL + p0) * DIc + d;
        ustride = DIc;
    } else {
        up = g_xs2 + ((size_t)((kz - 2) * TBc + tb) * LL + (LL - 1 - p0)) * DIc + d;
        ustride = -DIc;
    }
    const float* rowp = g_xdbl + ((size_t)kb * LL + p0) * C40;
    float* yp = g_ysT + ((size_t)kb * LL + p0) * DIc + d;

    if (pow_ok) {
        for (int i = 0; i < SEG; i++) {
            float dt, r;
            dt_from_row(rowp, wr, dbias, dt, r);
            const float u  = up[0];
            const float du = dt * u;
            float e[NSc];
            epow16(r, e);
            float acc = 0.f;
#pragma unroll
            for (int g = 0; g < 4; g++) {
                const float4 B = *(const float4*)(rowp + 8 + 4 * g);
                const float4 C = *(const float4*)(rowp + 24 + 4 * g);
                h[4*g+0] = fmaf(h[4*g+0], e[4*g+0], du * B.x); acc = fmaf(h[4*g+0], C.x, acc);
                h[4*g+1] = fmaf(h[4*g+1], e[4*g+1], du * B.y); acc = fmaf(h[4*g+1], C.y, acc);
                h[4*g+2] = fmaf(h[4*g+2], e[4*g+2], du * B.z); acc = fmaf(h[4*g+2], C.z, acc);
                h[4*g+3] = fmaf(h[4*g+3], e[4*g+3], du * B.w); acc = fmaf(h[4*g+3], C.w, acc);
            }
            yp[0] = acc + Dv * u;
            up += ustride; rowp += C40; yp += DIc;
        }
    } else {
        const float* Ap = A_logs + ad * NSc;
        for (int i = 0; i < SEG; i++) {
            float dt, r;
            dt_from_row(rowp, wr, dbias, dt, r);
            const float u  = up[0];
            const float du = dt * u;
            float acc = 0.f;
#pragma unroll
            for (int g = 0; g < 4; g++) {
                const float4 B  = *(const float4*)(rowp + 8 + 4 * g);
                const float4 C  = *(const float4*)(rowp + 24 + 4 * g);
                const float4 Al = *(const float4*)(Ap + 4 * g);
                h[4*g+0] = fmaf(h[4*g+0], __expf(-dt * __expf(Al.x)), du * B.x); acc = fmaf(h[4*g+0], C.x, acc);
                h[4*g+1] = fmaf(h[4*g+1], __expf(-dt * __expf(Al.y)), du * B.y); acc = fmaf(h[4*g+1], C.y, acc);
                h[4*g+2] = fmaf(h[4*g+2], __expf(-dt * __expf(Al.z)), du * B.z); acc = fmaf(h[4*g+2], C.z, acc);
                h[4*g+3] = fmaf(h[4*g+3], __expf(-dt * __expf(Al.w)), du * B.w); acc = fmaf(h[4*g+3], C.w, acc);
            }
            yp[0] = acc + Dv * u;
            up += ustride; rowp += C40; yp += DIc;
        }
    }
}

// ----------------- cross-merge + LayerNorm + SiLU gate ----------------------
__global__ __launch_bounds__(192) void merge_ln_gate_kernel(
    const float* __restrict__ ln_g, const float* __restrict__ ln_b)
{
    const int bid = blockIdx.x;
    const int tb  = bid / LL;
    const int l   = bid % LL;
    const int d   = threadIdx.x;
    const int h   = l / WW, w = l % WW;
    const int l2  = w * HH + h;

    float y = g_ysT[((size_t)(0 * TBc + tb) * LL + l)             * DIc + d]
            + g_ysT[((size_t)(1 * TBc + tb) * LL + l2)            * DIc + d]
            + g_ysT[((size_t)(2 * TBc + tb) * LL + (LL - 1 - l))  * DIc + d]
            + g_ysT[((size_t)(3 * TBc + tb) * LL + (LL - 1 - l2)) * DIc + d];

    float s = y, s2 = y * y;
#pragma unroll
    for (int o = 16; o > 0; o >>= 1) {
        s  += __shfl_xor_sync(0xffffffffu, s,  o);
        s2 += __shfl_xor_sync(0xffffffffu, s2, o);
    }
    __shared__ float sh[14];
    const int wid = d >> 5;
    if ((d & 31) == 0) { sh[wid] = s; sh[6 + wid] = s2; }
    __syncthreads();
    if (d == 0) {
        float ts = 0.f, ts2 = 0.f;
#pragma unroll
        for (int i = 0; i < 6; i++) { ts += sh[i]; ts2 += sh[6 + i]; }
        float mu  = ts * (1.0f / 192.0f);
        float var = ts2 * (1.0f / 192.0f) - mu * mu;
        sh[12] = mu;
        sh[13] = rsqrtf(var + 1e-5f);
    }
    __syncthreads();
    float mu = sh[12], rs = sh[13];

    float yn = (y - mu) * rs * ln_g[d] + ln_b[d];
    size_t zi = ((size_t)tb * LL + l) * DIc + d;
    float zv = g_z[zi];
    g_y[zi] = yn * siluf(zv);
}

// ------------------------------- launch -------------------------------------
extern "C" void kernel_launch(void* const* d_in, const int* in_sizes, int n_in,
                              void* d_out, int out_size)
{
    const float* x          = (const float*)d_in[0];
    const float* in_proj_w  = (const float*)d_in[1];
    const float* conv_w     = (const float*)d_in[2];
    const float* conv_b     = (const float*)d_in[3];
    const float* x_proj_w   = (const float*)d_in[4];
    const float* dt_w       = (const float*)d_in[5];
    const float* dt_b       = (const float*)d_in[6];
    const float* A_logs     = (const float*)d_in[7];
    const float* Ds         = (const float*)d_in[8];
    const float* ln_g       = (const float*)d_in[9];
    const float* ln_b       = (const float*)d_in[10];
    const float* out_proj_w = (const float*)d_in[11];
    const float* fc1_w      = (const float*)d_in[12];
    const float* fc1_b      = (const float*)d_in[13];
    const float* fc2_w      = (const float*)d_in[14];
    const float* fc2_b      = (const float*)d_in[15];
    float* out = (float*)d_out;

    float *pxs2 = nullptr, *py = nullptr, *pxf2 = nullptr, *ph1 = nullptr;
    cudaGetSymbolAddress((void**)&pxs2, g_xs2);
    cudaGetSymbolAddress((void**)&py,   g_y);
    cudaGetSymbolAddress((void**)&pxf2, g_xf2);
    cudaGetSymbolAddress((void**)&ph1,  g_h1);

    // 1. in_proj: (50176 x 96) @ (384 x 96)^T -> xi | z
    mma_gemm_kernel<EPI_INPROJ><<<dim3(6, M1c / 128), 256>>>(
        x, in_proj_w, nullptr, nullptr, nullptr, M1c, 384, Cc);

    // 2. depthwise conv + SiLU + cross-scan (dirs 0,1 only)
    conv_scan_kernel<<<TBc * HH, 192>>>(conv_w, conv_b);

    // 3. x_proj: per-direction (50176 x 192) @ (38 x 192)^T -> dts|B|C (padded)
    mma_gemm_kernel<EPI_XPROJ><<<dim3(1, M1c / 128, Kc), 256>>>(
        pxs2, x_proj_w, nullptr, nullptr, nullptr, M1c, C38, DIc);

    // 4. chunked selective scan (dt fused): state pass, prefix, full pass
    scan_pass1<<<(NCH * (NSEG - 1)) / 128, 128>>>(A_logs, dt_w, dt_b);
    scan_prefix<<<NCH / 128, 128>>>(A_logs);
    scan_pass2<<<(NCH * NSEG) / 128, 128>>>(A_logs, Ds, dt_w, dt_b);

    // 5. cross-merge + LayerNorm + SiLU(z) gate
    merge_ln_gate_kernel<<<TBc * LL, 192>>>(ln_g, ln_b);

    // 6. out_proj + residual 1 -> g_xf2
    mma_gemm_kernel<EPI_OUTPROJ><<<dim3(2, M1c / 128), 256>>>(
        py, out_proj_w, nullptr, x, nullptr, M1c, Cc, DIc);

    // 7. fc1 + bias + exact GELU -> g_h1
    mma_gemm_kernel<EPI_FC1><<<dim3(6, M1c / 128), 256>>>(
        pxf2, fc1_w, fc1_b, nullptr, nullptr, M1c, 4 * Cc, Cc);

    // 8. fc2 + bias + residual 2 -> d_out
    mma_gemm_kernel<EPI_FC2><<<dim3(2, M1c / 128), 256>>>(
        ph1, fc2_w, fc2_b, nullptr, out, M1c, Cc, 4 * Cc);
}